// round 15
// baseline (speedup 1.0000x reference)
#include <cuda_runtime.h>
#include <cuda_bf16.h>

#define EE 1024
#define BB 256
#define DIN 784
#define DH 400
#define DOUT 10
#define NT_A 416
#define PF 4
#define CAP_E 32768        // stream entries per sample (expected ~7000)
#define CEVT 64            // entries per l2 chunk

// Static device scratch (no cudaMalloc allowed)
__device__ float g_W1T[DIN * DH + 32];             // transposed W1 (+pad)
__device__ float g_W2r[(DH + 1) * DOUT];           // [401][10], row 400 = 0
__device__ float g_ms[(size_t)BB * CAP_E];         // stream: multiplier
__device__ unsigned short g_js[(size_t)BB * CAP_E];// stream: weight-row index
__device__ unsigned g_tot[BB];                     // padded stream length (or ~0 = overflow)
__device__ unsigned g_maskov[BB][EE][13];          // masks (overflow fallback only)

__global__ void prep_kernel(const float* __restrict__ W1,
                            const float* __restrict__ W2,
                            const float* __restrict__ b2) {
    int idx = blockIdx.x * blockDim.x + threadIdx.x;
    if (idx < DIN * DH) {
        int p = idx / DH;
        int j = idx - p * DH;
        g_W1T[idx] = W1[j * DIN + p];
    } else if (idx < DIN * DH + (DH + 1) * DOUT) {
        int i = idx - DIN * DH;
        int j = i / DOUT;
        int d = i - j * DOUT;
        g_W2r[i] = (j < DH)
            ? __fadd_rn(W2[d * DH + j], __fdiv_rn(b2[d], 400.0f))
            : 0.0f;
    }
}

#define A_SMEM ((EE + PF) * 8 + EE * 13 * 4 + EE * 4 * 3 + 32)

// Layer 1: one CTA/sample, 13 warps, depth-4 register prefetch, no barriers
// in main loop. Epilogue emits the uniform (m, j) FFMA stream.
__global__ __launch_bounds__(NT_A, 2) void l1_kernel(
    const float* __restrict__ times,
    const int*   __restrict__ pix,
    const float* __restrict__ b1)
{
    extern __shared__ unsigned char dyn[];
    float2*   s_ev   = (float2*)dyn;                   // [EE+PF] (decay1, byteoff)
    unsigned* s_mask = (unsigned*)(s_ev + EE + PF);    // [EE][13]
    float*    s_d2   = (float*)(s_mask + EE * 13);     // [EE]
    unsigned* s_ent  = (unsigned*)(s_d2 + EE);         // [EE] entries per event
    unsigned* s_off  = s_ent + EE;                     // [EE] exclusive prefix
    unsigned* s_T    = s_off + EE;                     // [1]

    const float TAUF = 0.6213349345596119f;  // float(-1/ln(0.2))
    const int b    = blockIdx.x;
    const int tid  = threadIdx.x;
    const int warp = tid >> 5;
    const int lane = tid & 31;

    for (int e = tid; e < EE; e += NT_A) {
        float t  = times[b * EE + e];
        float tp = (e > 0) ? times[b * EE + e - 1] : 0.0f;
        float d1 = expf(__fdiv_rn(-(t - tp), TAUF));
        float th  = __fadd_rn(t, 0.1f);
        float thp = (e > 0) ? __fadd_rn(tp, 0.1f) : 0.0f;
        s_d2[e] = expf(__fdiv_rn(-(th - thp), TAUF));
        int p = pix[b * EE + e];
        s_ev[e] = make_float2(d1, __int_as_float(p * (DH * 4)));
    }
    if (tid < PF) s_ev[EE + tid] = make_float2(1.0f, __int_as_float(0));
    __syncthreads();

    const bool valid = (tid < DH);
    float h1 = 0.0f;
    float bias1j = valid ? __fdiv_rn(b1[tid], 784.0f) : 0.0f;
    const char* w1b = (const char*)g_W1T + tid * 4;

    float wbuf[PF], dbuf[PF];
    #pragma unroll
    for (int i = 0; i < PF; ++i) {
        float2 ev = s_ev[i];
        dbuf[i] = ev.x;
        wbuf[i] = *(const float*)(w1b + __float_as_int(ev.y));
    }

    for (int e = 0; e < EE; e += PF) {
        #pragma unroll
        for (int u = 0; u < PF; ++u) {
            float2 evn = s_ev[e + u + PF];
            float d = dbuf[u], w = wbuf[u];
            dbuf[u] = evn.x;
            wbuf[u] = *(const float*)(w1b + __float_as_int(evn.y));

            h1 = __fadd_rn(__fadd_rn(__fmul_rn(h1, d), w), bias1j);
            bool fired = valid && (h1 >= 0.5f);
            h1 = fired ? 0.0f : h1;
            unsigned m = __ballot_sync(0xffffffffu, fired);
            if (lane == 0) s_mask[(e + u) * 13 + warp] = m;
        }
    }
    __syncthreads();

    // entries per event = 1 (decay) + n_spikes
    for (int e = tid; e < EE; e += NT_A) {
        int n = 0;
        #pragma unroll
        for (int w = 0; w < 13; ++w) n += __popc(s_mask[e * 13 + w]);
        s_ent[e] = (unsigned)(1 + n);
    }
    __syncthreads();

    // exclusive prefix scan (warp 0)
    if (warp == 0) {
        unsigned run = 0;
        for (int c = 0; c < EE / 32; ++c) {
            unsigned v = s_ent[c * 32 + lane];
            unsigned sc = v;
            #pragma unroll
            for (int d = 1; d < 32; d <<= 1) {
                unsigned u = __shfl_up_sync(0xffffffffu, sc, d);
                if (lane >= d) sc += u;
            }
            s_off[c * 32 + lane] = run + sc - v;
            run += __shfl_sync(0xffffffffu, sc, 31);
        }
        if (lane == 0) *s_T = run;
    }
    __syncthreads();

    const unsigned T = *s_T;
    const unsigned Tp = (T + (CEVT - 1)) & ~(unsigned)(CEVT - 1);

    if (Tp > CAP_E) {  // effectively never
        for (int i = tid; i < EE * 13; i += NT_A)
            (&g_maskov[b][0][0])[i] = s_mask[i];
        if (tid == 0) g_tot[b] = 0xFFFFFFFFu;
        return;
    }

    float* ms = g_ms + (size_t)b * CAP_E;
    unsigned short* js = g_js + (size_t)b * CAP_E;

    for (int e = warp; e < EE; e += 13) {
        unsigned off = s_off[e];
        if (lane == 0) { ms[off] = s_d2[e]; js[off] = (unsigned short)DH; }
        unsigned m = (lane < 13) ? s_mask[e * 13 + lane] : 0u;
        int c = __popc(m);
        int sc = c;
        #pragma unroll
        for (int d = 1; d < 32; d <<= 1) {
            int v = __shfl_up_sync(0xffffffffu, sc, d);
            if (lane >= d) sc += v;
        }
        int pos = sc - c;
        unsigned base = off + 1;
        while (m) {
            int bit = __ffs(m) - 1;
            m &= m - 1;
            ms[base + pos] = 1.0f;
            js[base + pos] = (unsigned short)(lane * 32 + bit);
            ++pos;
        }
    }
    // identity padding to chunk multiple
    for (unsigned i = T + tid; i < Tp; i += NT_A) {
        ms[i] = 1.0f;
        js[i] = (unsigned short)DH;
    }
    if (tid == 0) g_tot[b] = Tp;
}

// Layer 2: one warp per sample; lanes 0..9 run the uniform FFMA chain over
// the stream, cp.async-ring-buffered 4 chunks deep.
__global__ __launch_bounds__(32) void l2_kernel(
    const float* __restrict__ times,
    float*       __restrict__ out)
{
    __shared__ float s_W2p[(DH + 1) * DOUT];
    __shared__ __align__(16) float m_ring[4][CEVT];
    __shared__ __align__(16) unsigned short j_ring[4][CEVT];

    const int b    = blockIdx.x;
    const int lane = threadIdx.x;

    for (int i = lane; i < (DH + 1) * DOUT; i += 32) s_W2p[i] = g_W2r[i];
    const unsigned tot = g_tot[b];
    __syncwarp();

    float h2 = 0.0f, cnt = 0.0f;

    if (tot == 0xFFFFFFFFu) {
        // rare fallback: direct mask scan
        const float TAUF = 0.6213349345596119f;
        if (lane < DOUT) {
            for (int e = 0; e < EE; ++e) {
                float t   = times[b * EE + e];
                float tp  = (e > 0) ? times[b * EE + e - 1] : 0.0f;
                float th  = __fadd_rn(t, 0.1f);
                float thp = (e > 0) ? __fadd_rn(tp, 0.1f) : 0.0f;
                h2 = __fmul_rn(h2, expf(__fdiv_rn(-(th - thp), TAUF)));
                for (int w = 0; w < 13; ++w) {
                    unsigned m = g_maskov[b][e][w];
                    while (m) {
                        int bit = __ffs(m) - 1;
                        m &= m - 1;
                        int j = w * 32 + bit;
                        h2 = __fadd_rn(h2, s_W2p[j * DOUT + lane]);
                        if (h2 >= 0.5f) { cnt = __fadd_rn(cnt, 1.0f); h2 = 0.0f; }
                    }
                }
            }
            out[b * DOUT + lane] = __fdiv_rn(cnt, 64.0f);
        }
        return;
    }

    const float* ms = g_ms + (size_t)b * CAP_E;
    const unsigned short* js = g_js + (size_t)b * CAP_E;
    const int NC = (int)(tot / CEVT);   // >= 16 always

    // issue one chunk's cp.asyncs (lanes 0-15: m 256B, lanes 16-23: j 128B)
    auto issue = [&](int c) {
        int rb = c & 3;
        if (lane < 16) {
            unsigned dst = (unsigned)__cvta_generic_to_shared(&m_ring[rb][0]) + lane * 16;
            const char* src = (const char*)(ms + c * CEVT) + lane * 16;
            asm volatile("cp.async.ca.shared.global [%0], [%1], 16;" :: "r"(dst), "l"(src));
        } else if (lane < 24) {
            unsigned dst = (unsigned)__cvta_generic_to_shared(&j_ring[rb][0]) + (lane - 16) * 16;
            const char* src = (const char*)(js + c * CEVT) + (lane - 16) * 16;
            asm volatile("cp.async.ca.shared.global [%0], [%1], 16;" :: "r"(dst), "l"(src));
        }
        asm volatile("cp.async.commit_group;");
    };

    issue(0); issue(1); issue(2);

    for (int c = 0; c < NC; ++c) {
        asm volatile("cp.async.wait_group 2;");
        __syncwarp();
        if (lane < DOUT) {
            const int rb = c & 3;
            for (int i = 0; i < CEVT; i += 16) {
                #pragma unroll
                for (int u = 0; u < 16; ++u) {
                    float m = m_ring[rb][i + u];
                    int   j = j_ring[rb][i + u];
                    float w = s_W2p[j * DOUT + lane];
                    h2 = __fmaf_rn(h2, m, w);       // == FMUL (a=0) / FADD (m=1)
                    bool f = h2 >= 0.5f;
                    cnt = f ? __fadd_rn(cnt, 1.0f) : cnt;
                    h2 = f ? 0.0f : h2;
                }
            }
        }
        __syncwarp();
        if (c + 3 < NC) issue(c + 3);
        else asm volatile("cp.async.commit_group;");  // keep group counts uniform
    }

    if (lane < DOUT)
        out[b * DOUT + lane] = __fdiv_rn(cnt, 64.0f);
}

extern "C" void kernel_launch(void* const* d_in, const int* in_sizes, int n_in,
                              void* d_out, int out_size) {
    const float* times = (const float*)d_in[0];  // [256,1024] f32
    const int*   pixv  = (const int*)d_in[1];    // [256,1024] i32
    const float* W1    = (const float*)d_in[2];  // [400,784]
    const float* b1    = (const float*)d_in[3];  // [400]
    const float* W2    = (const float*)d_in[4];  // [10,400]
    const float* b2    = (const float*)d_in[5];  // [10]

    cudaFuncSetAttribute(l1_kernel,
                         cudaFuncAttributeMaxDynamicSharedMemorySize, A_SMEM);

    int prep_n = DIN * DH + (DH + 1) * DOUT;
    prep_kernel<<<(prep_n + 255) / 256, 256>>>(W1, W2, b2);
    l1_kernel<<<BB, NT_A, A_SMEM>>>(times, pixv, b1);
    l2_kernel<<<BB, 32>>>(times, (float*)d_out);
}

// round 16
// speedup vs baseline: 1.2671x; 1.2671x over previous
#include <cuda_runtime.h>
#include <cuda_bf16.h>

#define EE 1024
#define BB 256
#define DIN 784
#define DH 400
#define DOUT 10
#define PF 4
#define CEVT 64                 // events per chunk
#define NCH (EE / CEVT)         // 16 chunks
#define CAPC 1024               // stream entries per chunk buffer (avg ~450)
#define NT 448                  // 13 producer warps + 1 chain warp
#define OVF 0xFFFFFFFFu

#define BAR_SYNC(id, n)   asm volatile("bar.sync %0, %1;"   :: "r"(id), "r"(n) : "memory")
#define BAR_ARRIVE(id, n) asm volatile("bar.arrive %0, %1;" :: "r"(id), "r"(n) : "memory")

// Static device scratch (no cudaMalloc allowed)
__device__ float g_W1T[DIN * DH + 32];      // transposed W1 (+pad)
__device__ float g_W2r[(DH + 1) * DOUT];    // [401][10], row 400 = 0

__global__ void prep_kernel(const float* __restrict__ W1,
                            const float* __restrict__ W2,
                            const float* __restrict__ b2) {
    int idx = blockIdx.x * blockDim.x + threadIdx.x;
    if (idx < DIN * DH) {
        int p = idx / DH;
        int j = idx - p * DH;
        g_W1T[idx] = W1[j * DIN + p];
    } else if (idx < DIN * DH + (DH + 1) * DOUT) {
        int i = idx - DIN * DH;
        int j = i / DOUT;
        int d = i - j * DOUT;
        g_W2r[i] = (j < DH)
            ? __fadd_rn(W2[d * DH + j], __fdiv_rn(b2[d], 400.0f))
            : 0.0f;
    }
}

#define SM_BYTES ((EE + PF) * 8 + EE * 4 + (DH + 1) * DOUT * 4 \
                + 2 * CEVT * 13 * 4 + 2 * CAPC * 4 + 2 * CAPC * 2 \
                + 2 * CEVT * 4 + 2 * 4 + 64)

// Fused kernel: one CTA per sample.
//  warps 0..12 : layer-1 (400 neurons) -> masks -> compact (m,j) stream in SMEM
//  warp  13    : layer-2 FFMA chain, pipelined one chunk behind via named bars
// Barrier 1 (448): producers arrive "chunk ready", chain syncs.
// Barrier 2 (448): chain arrives "chunk consumed", producers sync (backpressure, depth 2).
// Barrier 3 (416): producer-internal (masks visible / offsets visible).
__global__ __launch_bounds__(NT, 2) void snn_fused(
    const float* __restrict__ times,
    const int*   __restrict__ pix,
    const float* __restrict__ b1,
    float*       __restrict__ out)
{
    extern __shared__ unsigned char dyn[];
    float2*         s_ev   = (float2*)dyn;                         // [EE+PF]
    float*          s_d2   = (float*)(s_ev + EE + PF);             // [EE]
    float*          s_W2p  = s_d2 + EE;                            // [401*10]
    unsigned*       s_mask = (unsigned*)(s_W2p + (DH + 1) * DOUT); // [2][CEVT][13]
    float*          s_m    = (float*)(s_mask + 2 * CEVT * 13);     // [2][CAPC]
    unsigned short* s_j    = (unsigned short*)(s_m + 2 * CAPC);    // [2][CAPC]
    unsigned*       s_off  = (unsigned*)(s_j + 2 * CAPC);          // [2][CEVT]
    unsigned*       s_T    = s_off + 2 * CEVT;                     // [2]

    const float TAUF = 0.6213349345596119f;  // float(-1/ln(0.2))
    const int b    = blockIdx.x;
    const int tid  = threadIdx.x;
    const int warp = tid >> 5;
    const int lane = tid & 31;

    // ---- prologue: event data, decays, W2 to shared ----
    for (int e = tid; e < EE; e += NT) {
        float t  = times[b * EE + e];
        float tp = (e > 0) ? times[b * EE + e - 1] : 0.0f;
        float d1 = expf(__fdiv_rn(-(t - tp), TAUF));
        float th  = __fadd_rn(t, 0.1f);
        float thp = (e > 0) ? __fadd_rn(tp, 0.1f) : 0.0f;
        s_d2[e] = expf(__fdiv_rn(-(th - thp), TAUF));
        int p = pix[b * EE + e];
        s_ev[e] = make_float2(d1, __int_as_float(p * (DH * 4)));
    }
    if (tid < PF) s_ev[EE + tid] = make_float2(1.0f, __int_as_float(0));
    for (int i = tid; i < (DH + 1) * DOUT; i += NT) s_W2p[i] = g_W2r[i];
    __syncthreads();

    if (warp < 13) {
        // =================== producers ===================
        const bool valid = (tid < DH);
        float h1 = 0.0f;
        float bias1j = valid ? __fdiv_rn(b1[tid], 784.0f) : 0.0f;
        const char* w1b = (const char*)g_W1T + tid * 4;

        float wbuf[PF], dbuf[PF];
        #pragma unroll
        for (int i = 0; i < PF; ++i) {
            float2 ev = s_ev[i];
            dbuf[i] = ev.x;
            wbuf[i] = *(const float*)(w1b + __float_as_int(ev.y));
        }

        for (int k = 0; k < NCH; ++k) {
            if (k >= 2) BAR_SYNC(2, NT);     // chain done with chunk k-2
            const int buf = k & 1;
            unsigned* mk = s_mask + buf * CEVT * 13;

            // ---- layer-1 over this chunk's 64 events ----
            for (int e0 = 0; e0 < CEVT; e0 += PF) {
                #pragma unroll
                for (int u = 0; u < PF; ++u) {
                    const int e = k * CEVT + e0 + u;
                    float2 evn = s_ev[e + PF];
                    float d = dbuf[u], w = wbuf[u];
                    dbuf[u] = evn.x;
                    wbuf[u] = *(const float*)(w1b + __float_as_int(evn.y));

                    h1 = __fadd_rn(__fadd_rn(__fmul_rn(h1, d), w), bias1j);
                    bool fired = valid && (h1 >= 0.5f);
                    h1 = fired ? 0.0f : h1;
                    unsigned m = __ballot_sync(0xffffffffu, fired);
                    if (lane == 0) mk[(e0 + u) * 13 + warp] = m;
                }
            }
            BAR_SYNC(3, 416);                // all masks of chunk k visible

            // ---- warp 0: counts + exclusive prefix + padding ----
            if (warp == 0) {
                unsigned c0 = 0, c1 = 0;
                #pragma unroll
                for (int w = 0; w < 13; ++w) {
                    c0 += __popc(mk[lane * 13 + w]);
                    c1 += __popc(mk[(lane + 32) * 13 + w]);
                }
                unsigned n0 = c0 + 1, n1 = c1 + 1;   // +1 decay entry
                unsigned s0 = n0;
                #pragma unroll
                for (int d = 1; d < 32; d <<= 1) {
                    unsigned v = __shfl_up_sync(0xffffffffu, s0, d);
                    if (lane >= d) s0 += v;
                }
                unsigned tot0 = __shfl_sync(0xffffffffu, s0, 31);
                unsigned s1 = n1;
                #pragma unroll
                for (int d = 1; d < 32; d <<= 1) {
                    unsigned v = __shfl_up_sync(0xffffffffu, s1, d);
                    if (lane >= d) s1 += v;
                }
                s1 += tot0;
                s_off[buf * CEVT + lane]      = s0 - n0;
                s_off[buf * CEVT + lane + 32] = s1 - n1;
                unsigned T  = __shfl_sync(0xffffffffu, s1, 31);
                unsigned Tp = (T + 7u) & ~7u;
                if (Tp <= CAPC) {
                    if (lane < Tp - T) {     // identity pad: m=1, w=0
                        s_m[buf * CAPC + T + lane] = 1.0f;
                        s_j[buf * CAPC + T + lane] = (unsigned short)DH;
                    }
                    if (lane == 0) s_T[buf] = Tp;
                } else if (lane == 0) {
                    s_T[buf] = OVF;
                }
            }
            BAR_SYNC(3, 416);                // offsets + s_T visible

            // ---- compaction: each warp a strided set of events ----
            if (s_T[buf] != OVF) {
                for (int e0 = warp; e0 < CEVT; e0 += 13) {
                    unsigned m = (lane < 13) ? mk[e0 * 13 + lane] : 0u;
                    int c = __popc(m);
                    int sc = c;
                    #pragma unroll
                    for (int d = 1; d < 32; d <<= 1) {
                        int v = __shfl_up_sync(0xffffffffu, sc, d);
                        if (lane >= d) sc += v;
                    }
                    unsigned off = s_off[buf * CEVT + e0];
                    if (lane == 0) {         // decay entry
                        s_m[buf * CAPC + off] = s_d2[k * CEVT + e0];
                        s_j[buf * CAPC + off] = (unsigned short)DH;
                    }
                    unsigned pos = off + 1 + (unsigned)(sc - c);
                    while (m) {
                        int bit = __ffs(m) - 1;
                        m &= m - 1;
                        s_m[buf * CAPC + pos] = 1.0f;
                        s_j[buf * CAPC + pos] = (unsigned short)(warp * 0 + lane * 32 + bit);
                        ++pos;
                    }
                }
            }
            BAR_ARRIVE(1, NT);               // chunk k ready for chain
        }
    } else {
        // =================== chain warp ===================
        float h2 = 0.0f, cnt = 0.0f;
        for (int k = 0; k < NCH; ++k) {
            BAR_SYNC(1, NT);                 // chunk k ready
            const int buf = k & 1;
            const unsigned Tp = s_T[buf];
            if (lane < DOUT) {
                if (Tp != OVF) {
                    const float* mm = s_m + buf * CAPC;
                    const unsigned short* jj = s_j + buf * CAPC;
                    for (unsigned i = 0; i < Tp; i += 8) {
                        #pragma unroll
                        for (int u = 0; u < 8; ++u) {
                            float m = mm[i + u];
                            int   j = jj[i + u];
                            float w = s_W2p[j * DOUT + lane];
                            h2 = __fmaf_rn(h2, m, w);   // decay (w=0) / spike (m=1)
                            bool f = h2 >= 0.5f;
                            cnt = f ? __fadd_rn(cnt, 1.0f) : cnt;
                            h2 = f ? 0.0f : h2;
                        }
                    }
                } else {
                    // rare overflow: scan masks directly, ascending j
                    const unsigned* mk = s_mask + buf * CEVT * 13;
                    for (int e0 = 0; e0 < CEVT; ++e0) {
                        h2 = __fmaf_rn(h2, s_d2[k * CEVT + e0], 0.0f);
                        bool f0 = h2 >= 0.5f;
                        cnt = f0 ? __fadd_rn(cnt, 1.0f) : cnt;
                        h2 = f0 ? 0.0f : h2;
                        for (int w = 0; w < 13; ++w) {
                            unsigned m = mk[e0 * 13 + w];
                            while (m) {
                                int bit = __ffs(m) - 1;
                                m &= m - 1;
                                int j = w * 32 + bit;
                                float wv = s_W2p[j * DOUT + lane];
                                h2 = __fmaf_rn(h2, 1.0f, wv);
                                bool f = h2 >= 0.5f;
                                cnt = f ? __fadd_rn(cnt, 1.0f) : cnt;
                                h2 = f ? 0.0f : h2;
                            }
                        }
                    }
                }
            }
            if (k < NCH - 2) BAR_ARRIVE(2, NT);   // free buffer for chunk k+2
        }
        if (lane < DOUT)
            out[b * DOUT + lane] = __fdiv_rn(cnt, 64.0f);
    }
}

extern "C" void kernel_launch(void* const* d_in, const int* in_sizes, int n_in,
                              void* d_out, int out_size) {
    const float* times = (const float*)d_in[0];  // [256,1024] f32
    const int*   pixv  = (const int*)d_in[1];    // [256,1024] i32
    const float* W1    = (const float*)d_in[2];  // [400,784]
    const float* b1    = (const float*)d_in[3];  // [400]
    const float* W2    = (const float*)d_in[4];  // [10,400]
    const float* b2    = (const float*)d_in[5];  // [10]

    static int attr_set = 0;
    if (!attr_set) {
        cudaFuncSetAttribute(snn_fused,
                             cudaFuncAttributeMaxDynamicSharedMemorySize,
                             SM_BYTES);
        attr_set = 1;
    }

    int prep_n = DIN * DH + (DH + 1) * DOUT;
    prep_kernel<<<(prep_n + 255) / 256, 256>>>(W1, W2, b2);
    snn_fused<<<BB, NT, SM_BYTES>>>(times, pixv, b1, (float*)d_out);
}